// round 2
// baseline (speedup 1.0000x reference)
#include <cuda_runtime.h>
#include <math.h>
#include <float.h>

// Problem constants
constexpr int CB  = 2;
constexpr int CS  = 2048;
constexpr int CE  = 2048;
constexpr int CH  = 16;
constexpr int CKV = 8;
constexpr int CD  = 128;
constexpr int CG  = CH / CKV;           // 2
constexpr int MROWS = CB * CS;          // 4096
constexpr int KVD   = CKV * CD;         // 1024
constexpr float RMS_EPS = 1.1920928955078125e-07f;  // float32 eps
constexpr float ATTN_SCALE = 0.08838834764831845f;  // 1/sqrt(128)

// Scratch (device globals; no runtime allocation allowed)
__device__ float g_q[MROWS * CE];       // 32 MB  (B,S,H,D)
__device__ float g_k[MROWS * KVD];      // 16 MB  (B,S,KV,D)
__device__ float g_v[MROWS * KVD];      // 16 MB
__device__ float g_attn[MROWS * CE];    // 32 MB  (B,S,H*D)

// ---------------------------------------------------------------------------
// SGEMM: C[M,N] = A[M,K] @ W[N,K]^T + bias[N]
// 128x128 tile, BK=8, 256 threads, 8x8 microtile.
// ---------------------------------------------------------------------------
__global__ __launch_bounds__(256) void sgemm_nt_bias(
    const float* __restrict__ A, const float* __restrict__ W,
    const float* __restrict__ bias, float* __restrict__ C,
    int Mdim, int Ndim, int Kdim)
{
    __shared__ __align__(16) float As[8][128];
    __shared__ __align__(16) float Bs[8][128];

    const int tid = threadIdx.x;
    const int tx = tid & 15;
    const int ty = tid >> 4;
    const int row0 = blockIdx.y * 128;
    const int col0 = blockIdx.x * 128;

    const int lr = tid >> 1;            // 0..127: tile row being loaded
    const int lk = (tid & 1) * 4;       // 0 or 4: k offset within BK
    const float* Aload = A + (size_t)(row0 + lr) * Kdim + lk;
    const float* Wload = W + (size_t)(col0 + lr) * Kdim + lk;

    float acc[8][8];
    #pragma unroll
    for (int i = 0; i < 8; i++)
        #pragma unroll
        for (int j = 0; j < 8; j++) acc[i][j] = 0.f;

    for (int k0 = 0; k0 < Kdim; k0 += 8) {
        float4 a4 = *reinterpret_cast<const float4*>(Aload + k0);
        float4 b4 = *reinterpret_cast<const float4*>(Wload + k0);
        As[lk + 0][lr] = a4.x; As[lk + 1][lr] = a4.y;
        As[lk + 2][lr] = a4.z; As[lk + 3][lr] = a4.w;
        Bs[lk + 0][lr] = b4.x; Bs[lk + 1][lr] = b4.y;
        Bs[lk + 2][lr] = b4.z; Bs[lk + 3][lr] = b4.w;
        __syncthreads();

        #pragma unroll
        for (int k = 0; k < 8; k++) {
            float a[8], b[8];
            *reinterpret_cast<float4*>(&a[0]) = *reinterpret_cast<const float4*>(&As[k][ty * 8]);
            *reinterpret_cast<float4*>(&a[4]) = *reinterpret_cast<const float4*>(&As[k][ty * 8 + 4]);
            *reinterpret_cast<float4*>(&b[0]) = *reinterpret_cast<const float4*>(&Bs[k][tx * 8]);
            *reinterpret_cast<float4*>(&b[4]) = *reinterpret_cast<const float4*>(&Bs[k][tx * 8 + 4]);
            #pragma unroll
            for (int i = 0; i < 8; i++)
                #pragma unroll
                for (int j = 0; j < 8; j++)
                    acc[i][j] += a[i] * b[j];
        }
        __syncthreads();
    }

    float bvals[8];
    #pragma unroll
    for (int j = 0; j < 8; j++) bvals[j] = bias[col0 + tx * 8 + j];

    #pragma unroll
    for (int i = 0; i < 8; i++) {
        float* crow = C + (size_t)(row0 + ty * 8 + i) * Ndim + col0 + tx * 8;
        float4 r0, r1;
        r0.x = acc[i][0] + bvals[0]; r0.y = acc[i][1] + bvals[1];
        r0.z = acc[i][2] + bvals[2]; r0.w = acc[i][3] + bvals[3];
        r1.x = acc[i][4] + bvals[4]; r1.y = acc[i][5] + bvals[5];
        r1.z = acc[i][6] + bvals[6]; r1.w = acc[i][7] + bvals[7];
        *reinterpret_cast<float4*>(&crow[0]) = r0;
        *reinterpret_cast<float4*>(&crow[4]) = r1;
    }
}

// ---------------------------------------------------------------------------
// RMSNorm over contiguous segments of 128 elements. One block per segment.
// ---------------------------------------------------------------------------
__global__ __launch_bounds__(128) void rmsnorm_kernel(
    float* __restrict__ buf, const float* __restrict__ w)
{
    __shared__ float red[4];
    float* p = buf + (size_t)blockIdx.x * CD;
    const int t = threadIdx.x;
    float v = p[t];
    float sq = v * v;
    #pragma unroll
    for (int o = 16; o > 0; o >>= 1) sq += __shfl_xor_sync(0xffffffffu, sq, o);
    if ((t & 31) == 0) red[t >> 5] = sq;
    __syncthreads();
    float ms = (red[0] + red[1] + red[2] + red[3]) * (1.0f / 128.0f);
    p[t] = v * rsqrtf(ms + RMS_EPS) * w[t];
}

// ---------------------------------------------------------------------------
// Flash attention (fp32, causal, GQA). Grid: (S/64, H, B). Block: 256 threads.
// 64-query tile, 64-key tiles, D=128. Q/K stored d-major (transposed) in smem
// with padded stride 68 so QK^T inner loop uses LDS.128 both sides.
// ---------------------------------------------------------------------------
constexpr int PADT = 68;  // padded stride for transposed Q/K tiles (16B aligned, conflict-light)
constexpr int FLASH_SMEM =
    (128 * PADT + 128 * PADT + 64 * 128 + 64 * 65) * (int)sizeof(float);  // 119040 B

__global__ __launch_bounds__(256) void flash_attn_kernel(
    const float* __restrict__ Q, const float* __restrict__ K,
    const float* __restrict__ V, float* __restrict__ O)
{
    extern __shared__ __align__(16) float sm[];
    float* Qst = sm;                     // [128][68]  (d-major)
    float* Kst = Qst + 128 * PADT;       // [128][68]  (d-major)
    float* Vs  = Kst + 128 * PADT;       // [64][128]  (key-major)
    float* Ps  = Vs + 64 * 128;          // [64][65]

    const int qt = blockIdx.x;
    const int h  = blockIdx.y;
    const int bb = blockIdx.z;
    const int kvh = h / CG;
    const int tid = threadIdx.x;
    const int tx = tid & 15;
    const int ty = tid >> 4;
    const int q0 = qt * 64;

    // Load Q tile transposed: 64 rows x 128 d -> 2048 float4, 8 per thread
    #pragma unroll
    for (int it = 0; it < 8; it++) {
        int idx = tid + it * 256;        // 0..2047
        int r  = idx >> 5;               // 0..63
        int dc = (idx & 31) * 4;         // 0..124
        float4 f = *reinterpret_cast<const float4*>(
            &Q[(size_t)(bb * CS + q0 + r) * CE + h * CD + dc]);
        Qst[(dc + 0) * PADT + r] = f.x;
        Qst[(dc + 1) * PADT + r] = f.y;
        Qst[(dc + 2) * PADT + r] = f.z;
        Qst[(dc + 3) * PADT + r] = f.w;
    }

    float o_acc[4][8];
    #pragma unroll
    for (int i = 0; i < 4; i++)
        #pragma unroll
        for (int j = 0; j < 8; j++) o_acc[i][j] = 0.f;
    float m_i[4], l_i[4];
    #pragma unroll
    for (int i = 0; i < 4; i++) { m_i[i] = -INFINITY; l_i[i] = 0.f; }

    for (int kt = 0; kt <= qt; kt++) {
        const int k0 = kt * 64;
        __syncthreads();  // protect Kst/Vs/Ps against readers of previous tile

        // Load K (transposed) and V tiles
        #pragma unroll
        for (int it = 0; it < 8; it++) {
            int idx = tid + it * 256;
            int r  = idx >> 5;
            int dc = (idx & 31) * 4;
            const size_t grow = (size_t)(bb * CS + k0 + r) * KVD + kvh * CD + dc;
            float4 f = *reinterpret_cast<const float4*>(&K[grow]);
            Kst[(dc + 0) * PADT + r] = f.x;
            Kst[(dc + 1) * PADT + r] = f.y;
            Kst[(dc + 2) * PADT + r] = f.z;
            Kst[(dc + 3) * PADT + r] = f.w;
            float4 g = *reinterpret_cast<const float4*>(&V[grow]);
            *reinterpret_cast<float4*>(&Vs[r * 128 + dc]) = g;
        }
        __syncthreads();

        // S = Q @ K^T  (64x64, thread owns rows 4ty..4ty+3, cols 4tx..4tx+3)
        float sacc[4][4];
        #pragma unroll
        for (int i = 0; i < 4; i++)
            #pragma unroll
            for (int j = 0; j < 4; j++) sacc[i][j] = 0.f;

        #pragma unroll 4
        for (int k = 0; k < 128; k++) {
            float4 aq = *reinterpret_cast<const float4*>(&Qst[k * PADT + ty * 4]);
            float4 bk = *reinterpret_cast<const float4*>(&Kst[k * PADT + tx * 4]);
            float av[4] = {aq.x, aq.y, aq.z, aq.w};
            float bv[4] = {bk.x, bk.y, bk.z, bk.w};
            #pragma unroll
            for (int i = 0; i < 4; i++)
                #pragma unroll
                for (int j = 0; j < 4; j++)
                    sacc[i][j] += av[i] * bv[j];
        }

        // scale + causal mask (mask only needed on diagonal tile)
        if (kt == qt) {
            #pragma unroll
            for (int i = 0; i < 4; i++) {
                const int gr = ty * 4 + i;
                #pragma unroll
                for (int j = 0; j < 4; j++) {
                    const int gc = tx * 4 + j;
                    float sv = sacc[i][j] * ATTN_SCALE;
                    sacc[i][j] = (gc > gr) ? -1e30f : sv;
                }
            }
        } else {
            #pragma unroll
            for (int i = 0; i < 4; i++)
                #pragma unroll
                for (int j = 0; j < 4; j++)
                    sacc[i][j] *= ATTN_SCALE;
        }

        // Online softmax per row (16 threads per row, shfl width 16)
        #pragma unroll
        for (int i = 0; i < 4; i++) {
            float mx = fmaxf(fmaxf(sacc[i][0], sacc[i][1]), fmaxf(sacc[i][2], sacc[i][3]));
            #pragma unroll
            for (int o = 8; o > 0; o >>= 1)
                mx = fmaxf(mx, __shfl_xor_sync(0xffffffffu, mx, o, 16));
            const float mnew = fmaxf(m_i[i], mx);
            const float corr = __expf(m_i[i] - mnew);
            float rs = 0.f;
            #pragma unroll
            for (int j = 0; j < 4; j++) {
                float p = __expf(sacc[i][j] - mnew);
                sacc[i][j] = p;
                rs += p;
            }
            #pragma unroll
            for (int o = 8; o > 0; o >>= 1)
                rs += __shfl_xor_sync(0xffffffffu, rs, o, 16);
            l_i[i] = l_i[i] * corr + rs;
            m_i[i] = mnew;
            #pragma unroll
            for (int j2 = 0; j2 < 8; j2++) o_acc[i][j2] *= corr;
            #pragma unroll
            for (int j = 0; j < 4; j++)
                Ps[(ty * 4 + i) * 65 + tx * 4 + j] = sacc[i][j];
        }
        __syncthreads();

        // O += P @ V  (thread owns rows 4ty..4ty+3, d-cols 8tx..8tx+7)
        #pragma unroll 4
        for (int c = 0; c < 64; c++) {
            float pp[4];
            #pragma unroll
            for (int i = 0; i < 4; i++) pp[i] = Ps[(ty * 4 + i) * 65 + c];
            float4 va = *reinterpret_cast<const float4*>(&Vs[c * 128 + tx * 8]);
            float4 vb = *reinterpret_cast<const float4*>(&Vs[c * 128 + tx * 8 + 4]);
            float vv[8] = {va.x, va.y, va.z, va.w, vb.x, vb.y, vb.z, vb.w};
            #pragma unroll
            for (int i = 0; i < 4; i++)
                #pragma unroll
                for (int j2 = 0; j2 < 8; j2++)
                    o_acc[i][j2] += pp[i] * vv[j2];
        }
    }

    // Epilogue: normalize and store to (B,S,H*D)
    #pragma unroll
    for (int i = 0; i < 4; i++) {
        const float inv = 1.0f / l_i[i];
        float* orow = O + (size_t)(bb * CS + q0 + ty * 4 + i) * CE + h * CD + tx * 8;
        float4 r0, r1;
        r0.x = o_acc[i][0] * inv; r0.y = o_acc[i][1] * inv;
        r0.z = o_acc[i][2] * inv; r0.w = o_acc[i][3] * inv;
        r1.x = o_acc[i][4] * inv; r1.y = o_acc[i][5] * inv;
        r1.z = o_acc[i][6] * inv; r1.w = o_acc[i][7] * inv;
        *reinterpret_cast<float4*>(&orow[0]) = r0;
        *reinterpret_cast<float4*>(&orow[4]) = r1;
    }
}

// ---------------------------------------------------------------------------
// Launch
// ---------------------------------------------------------------------------
extern "C" void kernel_launch(void* const* d_in, const int* in_sizes, int n_in,
                              void* d_out, int out_size)
{
    (void)in_sizes; (void)n_in; (void)out_size;
    const float* x  = (const float*)d_in[0];
    const float* Wq = (const float*)d_in[1];
    const float* bq = (const float*)d_in[2];
    const float* Wk = (const float*)d_in[3];
    const float* bk = (const float*)d_in[4];
    const float* Wv = (const float*)d_in[5];
    const float* bv = (const float*)d_in[6];
    const float* Wo = (const float*)d_in[7];
    const float* bo = (const float*)d_in[8];
    const float* qn = (const float*)d_in[9];
    const float* kn = (const float*)d_in[10];
    float* out = (float*)d_out;

    float *q, *k, *v, *attn;
    cudaGetSymbolAddress((void**)&q,    g_q);
    cudaGetSymbolAddress((void**)&k,    g_k);
    cudaGetSymbolAddress((void**)&v,    g_v);
    cudaGetSymbolAddress((void**)&attn, g_attn);

    (void)cudaFuncSetAttribute(flash_attn_kernel,
                               cudaFuncAttributeMaxDynamicSharedMemorySize,
                               FLASH_SMEM);

    dim3 gE(CE / 128, MROWS / 128);    // (16, 32)
    dim3 gKV(KVD / 128, MROWS / 128);  // (8, 32)

    sgemm_nt_bias<<<gE, 256>>>(x, Wq, bq, q, MROWS, CE, CE);
    sgemm_nt_bias<<<gKV, 256>>>(x, Wk, bk, k, MROWS, KVD, CE);
    sgemm_nt_bias<<<gKV, 256>>>(x, Wv, bv, v, MROWS, KVD, CE);

    rmsnorm_kernel<<<MROWS * CH, 128>>>(q, qn);
    rmsnorm_kernel<<<MROWS * CKV, 128>>>(k, kn);

    dim3 ga(CS / 64, CH, CB);
    flash_attn_kernel<<<ga, 256, FLASH_SMEM>>>(q, k, v, attn);

    sgemm_nt_bias<<<gE, 256>>>(attn, Wo, bo, out, MROWS, CE, CE);
}

// round 5
// speedup vs baseline: 1.1865x; 1.1865x over previous
#include <cuda_runtime.h>
#include <math.h>
#include <float.h>
#include <stdint.h>

// Problem constants
constexpr int CB  = 2;
constexpr int CS  = 2048;
constexpr int CE  = 2048;
constexpr int CH  = 16;
constexpr int CKV = 8;
constexpr int CD  = 128;
constexpr int CG  = CH / CKV;           // 2
constexpr int MROWS = CB * CS;          // 4096
constexpr int KVD   = CKV * CD;         // 1024
constexpr float RMS_EPS = 1.1920928955078125e-07f;  // float32 eps
constexpr float ATTN_SCALE = 0.08838834764831845f;  // 1/sqrt(128)

// Scratch (device globals; no runtime allocation allowed)
__device__ float g_q[MROWS * CE];       // 32 MB  (B,S,H,D)
__device__ float g_k[MROWS * KVD];      // 16 MB  (B,S,KV,D)
__device__ float g_v[MROWS * KVD];      // 16 MB
__device__ float g_attn[MROWS * CE];    // 32 MB  (B,S,H*D)

// ---------------------------------------------------------------------------
// 3xTF32 tensor-core GEMM: C[M,N] = A[M,K] @ W[N,K]^T + bias[N]
// Block tile 128x128, BK=16, 256 threads (8 warps, 2x4), warp tile 64x32.
// Each operand split into hi=tf32(x), lo=x-hi; D += Ah*Bh + Ah*Bl + Al*Bh.
// ---------------------------------------------------------------------------
constexpr int SAS    = 20;              // smem row stride (floats): conflict-free for frag loads
constexpr int TILEF  = 128 * SAS;       // floats per (matrix, hi/lo) tile = 2560
constexpr int STAGEF = 4 * TILEF;       // Ahi, Alo, Whi, Wlo
constexpr int GEMM_SMEM = 2 * STAGEF * (int)sizeof(float);  // 81920 B

__device__ __forceinline__ uint32_t f2tf(float x) {
    uint32_t r;
    asm("cvt.rna.tf32.f32 %0, %1;" : "=r"(r) : "f"(x));
    return r;
}

__device__ __forceinline__ void mma_tf32(float (&c)[4],
    uint32_t a0, uint32_t a1, uint32_t a2, uint32_t a3,
    uint32_t b0, uint32_t b1)
{
    asm volatile(
        "mma.sync.aligned.m16n8k8.row.col.f32.tf32.tf32.f32 "
        "{%0,%1,%2,%3},{%4,%5,%6,%7},{%8,%9},{%0,%1,%2,%3};"
        : "+f"(c[0]), "+f"(c[1]), "+f"(c[2]), "+f"(c[3])
        : "r"(a0), "r"(a1), "r"(a2), "r"(a3), "r"(b0), "r"(b1));
}

__global__ __launch_bounds__(256) void gemm_tf32x3_nt_bias(
    const float* __restrict__ A, const float* __restrict__ W,
    const float* __restrict__ bias, float* __restrict__ C,
    int Ndim, int Kdim)
{
    extern __shared__ __align__(16) float smg[];
    const int tid  = threadIdx.x;
    const int warp = tid >> 5, lane = tid & 31;
    const int wm = warp & 1, wn = warp >> 1;     // 2 x 4 warp grid
    const int grp = lane >> 2, qd = lane & 3;
    const int row0 = blockIdx.y * 128;
    const int col0 = blockIdx.x * 128;

    // gmem load pattern: 512 float4 per matrix tile, 2 per thread
    const int ar = tid >> 2;                     // 0..63 (rows ar and ar+64)
    const int kq = (tid & 3) << 2;               // 0,4,8,12
    const float* Ap = A + (size_t)row0 * Kdim;
    const float* Wp = W + (size_t)col0 * Kdim;

    float acc[4][4][4];
    #pragma unroll
    for (int i = 0; i < 4; i++)
        #pragma unroll
        for (int j = 0; j < 4; j++)
            #pragma unroll
            for (int c = 0; c < 4; c++) acc[i][j][c] = 0.f;

    float4 ra0, ra1, rw0, rw1;
    const int NK = Kdim / 16;

    // prologue load of k-step 0
    {
        ra0 = *(const float4*)&Ap[(size_t)ar * Kdim + kq];
        ra1 = *(const float4*)&Ap[(size_t)(ar + 64) * Kdim + kq];
        rw0 = *(const float4*)&Wp[(size_t)ar * Kdim + kq];
        rw1 = *(const float4*)&Wp[(size_t)(ar + 64) * Kdim + kq];
    }

    for (int ks = 0; ks < NK; ks++) {
        // split + store current staged regs into stage ks&1
        {
            float* st = smg + (ks & 1) * STAGEF;
            float* hA = st;
            float* lA = st + TILEF;
            float* hW = st + 2 * TILEF;
            float* lW = st + 3 * TILEF;
            const int o0 = ar * SAS + kq;
            const int o1 = (ar + 64) * SAS + kq;
            float4 h, l;
            h.x = __uint_as_float(f2tf(ra0.x)); h.y = __uint_as_float(f2tf(ra0.y));
            h.z = __uint_as_float(f2tf(ra0.z)); h.w = __uint_as_float(f2tf(ra0.w));
            l.x = ra0.x - h.x; l.y = ra0.y - h.y; l.z = ra0.z - h.z; l.w = ra0.w - h.w;
            *(float4*)&hA[o0] = h; *(float4*)&lA[o0] = l;
            h.x = __uint_as_float(f2tf(ra1.x)); h.y = __uint_as_float(f2tf(ra1.y));
            h.z = __uint_as_float(f2tf(ra1.z)); h.w = __uint_as_float(f2tf(ra1.w));
            l.x = ra1.x - h.x; l.y = ra1.y - h.y; l.z = ra1.z - h.z; l.w = ra1.w - h.w;
            *(float4*)&hA[o1] = h; *(float4*)&lA[o1] = l;
            h.x = __uint_as_float(f2tf(rw0.x)); h.y = __uint_as_float(f2tf(rw0.y));
            h.z = __uint_as_float(f2tf(rw0.z)); h.w = __uint_as_float(f2tf(rw0.w));
            l.x = rw0.x - h.x; l.y = rw0.y - h.y; l.z = rw0.z - h.z; l.w = rw0.w - h.w;
            *(float4*)&hW[o0] = h; *(float4*)&lW[o0] = l;
            h.x = __uint_as_float(f2tf(rw1.x)); h.y = __uint_as_float(f2tf(rw1.y));
            h.z = __uint_as_float(f2tf(rw1.z)); h.w = __uint_as_float(f2tf(rw1.w));
            l.x = rw1.x - h.x; l.y = rw1.y - h.y; l.z = rw1.z - h.z; l.w = rw1.w - h.w;
            *(float4*)&hW[o1] = h; *(float4*)&lW[o1] = l;
        }
        __syncthreads();

        // prefetch next k-step from gmem
        if (ks + 1 < NK) {
            const int k0 = (ks + 1) * 16;
            ra0 = *(const float4*)&Ap[(size_t)ar * Kdim + k0 + kq];
            ra1 = *(const float4*)&Ap[(size_t)(ar + 64) * Kdim + k0 + kq];
            rw0 = *(const float4*)&Wp[(size_t)ar * Kdim + k0 + kq];
            rw1 = *(const float4*)&Wp[(size_t)(ar + 64) * Kdim + k0 + kq];
        }

        // compute on stage ks&1
        {
            const float* st = smg + (ks & 1) * STAGEF;
            const uint32_t* uAh = (const uint32_t*)st;
            const uint32_t* uAl = uAh + TILEF;
            const uint32_t* uWh = uAl + TILEF;
            const uint32_t* uWl = uWh + TILEF;

            #pragma unroll
            for (int k8 = 0; k8 < 16; k8 += 8) {
                uint32_t ah[4][4], al[4][4], bh[4][2], bl[4][2];
                #pragma unroll
                for (int mt = 0; mt < 4; mt++) {
                    const int m = wm * 64 + mt * 16;
                    const int o0 = (m + grp) * SAS + k8 + qd;
                    const int o1 = (m + 8 + grp) * SAS + k8 + qd;
                    ah[mt][0] = uAh[o0]; ah[mt][1] = uAh[o1];
                    ah[mt][2] = uAh[o0 + 4]; ah[mt][3] = uAh[o1 + 4];
                    al[mt][0] = uAl[o0]; al[mt][1] = uAl[o1];
                    al[mt][2] = uAl[o0 + 4]; al[mt][3] = uAl[o1 + 4];
                }
                #pragma unroll
                for (int nt = 0; nt < 4; nt++) {
                    const int n = wn * 32 + nt * 8;
                    const int o = (n + grp) * SAS + k8 + qd;
                    bh[nt][0] = uWh[o]; bh[nt][1] = uWh[o + 4];
                    bl[nt][0] = uWl[o]; bl[nt][1] = uWl[o + 4];
                }
                // pass 1: Ah * Bh
                #pragma unroll
                for (int mt = 0; mt < 4; mt++)
                    #pragma unroll
                    for (int nt = 0; nt < 4; nt++)
                        mma_tf32(acc[mt][nt], ah[mt][0], ah[mt][1], ah[mt][2], ah[mt][3],
                                 bh[nt][0], bh[nt][1]);
                // pass 2: Ah * Bl
                #pragma unroll
                for (int mt = 0; mt < 4; mt++)
                    #pragma unroll
                    for (int nt = 0; nt < 4; nt++)
                        mma_tf32(acc[mt][nt], ah[mt][0], ah[mt][1], ah[mt][2], ah[mt][3],
                                 bl[nt][0], bl[nt][1]);
                // pass 3: Al * Bh
                #pragma unroll
                for (int mt = 0; mt < 4; mt++)
                    #pragma unroll
                    for (int nt = 0; nt < 4; nt++)
                        mma_tf32(acc[mt][nt], al[mt][0], al[mt][1], al[mt][2], al[mt][3],
                                 bh[nt][0], bh[nt][1]);
            }
        }
        __syncthreads();
    }

    // epilogue: add bias, store
    #pragma unroll
    for (int mt = 0; mt < 4; mt++) {
        const int row = row0 + wm * 64 + mt * 16 + grp;
        #pragma unroll
        for (int nt = 0; nt < 4; nt++) {
            const int col = col0 + wn * 32 + nt * 8 + 2 * qd;
            const float b0 = bias[col], b1 = bias[col + 1];
            float2 v0, v1;
            v0.x = acc[mt][nt][0] + b0; v0.y = acc[mt][nt][1] + b1;
            v1.x = acc[mt][nt][2] + b0; v1.y = acc[mt][nt][3] + b1;
            *(float2*)&C[(size_t)row * Ndim + col] = v0;
            *(float2*)&C[(size_t)(row + 8) * Ndim + col] = v1;
        }
    }
}

// ---------------------------------------------------------------------------
// RMSNorm over contiguous segments of 128 elements. One block per segment.
// ---------------------------------------------------------------------------
__global__ __launch_bounds__(128) void rmsnorm_kernel(
    float* __restrict__ buf, const float* __restrict__ w)
{
    __shared__ float red[4];
    float* p = buf + (size_t)blockIdx.x * CD;
    const int t = threadIdx.x;
    float v = p[t];
    float sq = v * v;
    #pragma unroll
    for (int o = 16; o > 0; o >>= 1) sq += __shfl_xor_sync(0xffffffffu, sq, o);
    if ((t & 31) == 0) red[t >> 5] = sq;
    __syncthreads();
    float ms = (red[0] + red[1] + red[2] + red[3]) * (1.0f / 128.0f);
    p[t] = v * rsqrtf(ms + RMS_EPS) * w[t];
}

// ---------------------------------------------------------------------------
// Flash attention (fp32, causal, GQA). Grid: (S/64, H, B). Block: 256 threads.
// ---------------------------------------------------------------------------
constexpr int PADT = 68;
constexpr int FLASH_SMEM =
    (128 * PADT + 128 * PADT + 64 * 128 + 64 * 65) * (int)sizeof(float);  // 119040 B

__global__ __launch_bounds__(256) void flash_attn_kernel(
    const float* __restrict__ Q, const float* __restrict__ K,
    const float* __restrict__ V, float* __restrict__ O)
{
    extern __shared__ __align__(16) float sm[];
    float* Qst = sm;                     // [128][68]  (d-major)
    float* Kst = Qst + 128 * PADT;       // [128][68]  (d-major)
    float* Vs  = Kst + 128 * PADT;       // [64][128]  (key-major)
    float* Ps  = Vs + 64 * 128;          // [64][65]

    const int qt = blockIdx.x;
    const int h  = blockIdx.y;
    const int bb = blockIdx.z;
    const int kvh = h / CG;
    const int tid = threadIdx.x;
    const int tx = tid & 15;
    const int ty = tid >> 4;
    const int q0 = qt * 64;

    #pragma unroll
    for (int it = 0; it < 8; it++) {
        int idx = tid + it * 256;
        int r  = idx >> 5;
        int dc = (idx & 31) * 4;
        float4 f = *reinterpret_cast<const float4*>(
            &Q[(size_t)(bb * CS + q0 + r) * CE + h * CD + dc]);
        Qst[(dc + 0) * PADT + r] = f.x;
        Qst[(dc + 1) * PADT + r] = f.y;
        Qst[(dc + 2) * PADT + r] = f.z;
        Qst[(dc + 3) * PADT + r] = f.w;
    }

    float o_acc[4][8];
    #pragma unroll
    for (int i = 0; i < 4; i++)
        #pragma unroll
        for (int j = 0; j < 8; j++) o_acc[i][j] = 0.f;
    float m_i[4], l_i[4];
    #pragma unroll
    for (int i = 0; i < 4; i++) { m_i[i] = -INFINITY; l_i[i] = 0.f; }

    for (int kt = 0; kt <= qt; kt++) {
        const int k0 = kt * 64;
        __syncthreads();

        #pragma unroll
        for (int it = 0; it < 8; it++) {
            int idx = tid + it * 256;
            int r  = idx >> 5;
            int dc = (idx & 31) * 4;
            const size_t grow = (size_t)(bb * CS + k0 + r) * KVD + kvh * CD + dc;
            float4 f = *reinterpret_cast<const float4*>(&K[grow]);
            Kst[(dc + 0) * PADT + r] = f.x;
            Kst[(dc + 1) * PADT + r] = f.y;
            Kst[(dc + 2) * PADT + r] = f.z;
            Kst[(dc + 3) * PADT + r] = f.w;
            float4 g = *reinterpret_cast<const float4*>(&V[grow]);
            *reinterpret_cast<float4*>(&Vs[r * 128 + dc]) = g;
        }
        __syncthreads();

        float sacc[4][4];
        #pragma unroll
        for (int i = 0; i < 4; i++)
            #pragma unroll
            for (int j = 0; j < 4; j++) sacc[i][j] = 0.f;

        #pragma unroll 4
        for (int k = 0; k < 128; k++) {
            float4 aq = *reinterpret_cast<const float4*>(&Qst[k * PADT + ty * 4]);
            float4 bk = *reinterpret_cast<const float4*>(&Kst[k * PADT + tx * 4]);
            float av[4] = {aq.x, aq.y, aq.z, aq.w};
            float bv[4] = {bk.x, bk.y, bk.z, bk.w};
            #pragma unroll
            for (int i = 0; i < 4; i++)
                #pragma unroll
                for (int j = 0; j < 4; j++)
                    sacc[i][j] += av[i] * bv[j];
        }

        if (kt == qt) {
            #pragma unroll
            for (int i = 0; i < 4; i++) {
                const int gr = ty * 4 + i;
                #pragma unroll
                for (int j = 0; j < 4; j++) {
                    const int gc = tx * 4 + j;
                    float sv = sacc[i][j] * ATTN_SCALE;
                    sacc[i][j] = (gc > gr) ? -1e30f : sv;
                }
            }
        } else {
            #pragma unroll
            for (int i = 0; i < 4; i++)
                #pragma unroll
                for (int j = 0; j < 4; j++)
                    sacc[i][j] *= ATTN_SCALE;
        }

        #pragma unroll
        for (int i = 0; i < 4; i++) {
            float mx = fmaxf(fmaxf(sacc[i][0], sacc[i][1]), fmaxf(sacc[i][2], sacc[i][3]));
            #pragma unroll
            for (int o = 8; o > 0; o >>= 1)
                mx = fmaxf(mx, __shfl_xor_sync(0xffffffffu, mx, o, 16));
            const float mnew = fmaxf(m_i[i], mx);
            const float corr = __expf(m_i[i] - mnew);
            float rs = 0.f;
            #pragma unroll
            for (int j = 0; j < 4; j++) {
                float p = __expf(sacc[i][j] - mnew);
                sacc[i][j] = p;
                rs += p;
            }
            #pragma unroll
            for (int o = 8; o > 0; o >>= 1)
                rs += __shfl_xor_sync(0xffffffffu, rs, o, 16);
            l_i[i] = l_i[i] * corr + rs;
            m_i[i] = mnew;
            #pragma unroll
            for (int j2 = 0; j2 < 8; j2++) o_acc[i][j2] *= corr;
            #pragma unroll
            for (int j = 0; j < 4; j++)
                Ps[(ty * 4 + i) * 65 + tx * 4 + j] = sacc[i][j];
        }
        __syncthreads();

        #pragma unroll 4
        for (int c = 0; c < 64; c++) {
            float pp[4];
            #pragma unroll
            for (int i = 0; i < 4; i++) pp[i] = Ps[(ty * 4 + i) * 65 + c];
            float4 va = *reinterpret_cast<const float4*>(&Vs[c * 128 + tx * 8]);
            float4 vb = *reinterpret_cast<const float4*>(&Vs[c * 128 + tx * 8 + 4]);
            float vv[8] = {va.x, va.y, va.z, va.w, vb.x, vb.y, vb.z, vb.w};
            #pragma unroll
            for (int i = 0; i < 4; i++)
                #pragma unroll
                for (int j2 = 0; j2 < 8; j2++)
                    o_acc[i][j2] += pp[i] * vv[j2];
        }
    }

    #pragma unroll
    for (int i = 0; i < 4; i++) {
        const float inv = 1.0f / l_i[i];
        float* orow = O + (size_t)(bb * CS + q0 + ty * 4 + i) * CE + h * CD + tx * 8;
        float4 r0, r1;
        r0.x = o_acc[i][0] * inv; r0.y = o_acc[i][1] * inv;
        r0.z = o_acc[i][2] * inv; r0.w = o_acc[i][3] * inv;
        r1.x = o_acc[i][4] * inv; r1.y = o_acc[i][5] * inv;
        r1.z = o_acc[i][6] * inv; r1.w = o_acc[i][7] * inv;
        *reinterpret_cast<float4*>(&orow[0]) = r0;
        *reinterpret_cast<float4*>(&orow[4]) = r1;
    }
}

// ---------------------------------------------------------------------------
// Launch
// ---------------------------------------------------------------------------
extern "C" void kernel_launch(void* const* d_in, const int* in_sizes, int n_in,
                              void* d_out, int out_size)
{
    (void)in_sizes; (void)n_in; (void)out_size;
    const float* x  = (const float*)d_in[0];
    const float* Wq = (const float*)d_in[1];
    const float* bq = (const float*)d_in[2];
    const float* Wk = (const float*)d_in[3];
    const float* bk = (const float*)d_in[4];
    const float* Wv = (const float*)d_in[5];
    const float* bv = (const float*)d_in[6];
    const float* Wo = (const float*)d_in[7];
    const float* bo = (const float*)d_in[8];
    const float* qn = (const float*)d_in[9];
    const float* kn = (const float*)d_in[10];
    float* out = (float*)d_out;

    float *q, *k, *v, *attn;
    cudaGetSymbolAddress((void**)&q,    g_q);
    cudaGetSymbolAddress((void**)&k,    g_k);
    cudaGetSymbolAddress((void**)&v,    g_v);
    cudaGetSymbolAddress((void**)&attn, g_attn);

    (void)cudaFuncSetAttribute(gemm_tf32x3_nt_bias,
                               cudaFuncAttributeMaxDynamicSharedMemorySize,
                               GEMM_SMEM);
    (void)cudaFuncSetAttribute(flash_attn_kernel,
                               cudaFuncAttributeMaxDynamicSharedMemorySize,
                               FLASH_SMEM);

    dim3 gE(CE / 128, MROWS / 128);    // (16, 32)
    dim3 gKV(KVD / 128, MROWS / 128);  // (8, 32)

    gemm_tf32x3_nt_bias<<<gE, 256, GEMM_SMEM>>>(x, Wq, bq, q, CE, CE);
    gemm_tf32x3_nt_bias<<<gKV, 256, GEMM_SMEM>>>(x, Wk, bk, k, KVD, CE);
    gemm_tf32x3_nt_bias<<<gKV, 256, GEMM_SMEM>>>(x, Wv, bv, v, KVD, CE);

    rmsnorm_kernel<<<MROWS * CH, 128>>>(q, qn);
    rmsnorm_kernel<<<MROWS * CKV, 128>>>(k, kn);

    dim3 ga(CS / 64, CH, CB);
    flash_attn_kernel<<<ga, 256, FLASH_SMEM>>>(q, k, v, attn);

    gemm_tf32x3_nt_bias<<<gE, 256, GEMM_SMEM>>>(attn, Wo, bo, out, CE, CE);
}

// round 7
// speedup vs baseline: 2.3169x; 1.9527x over previous
#include <cuda_runtime.h>
#include <cuda_bf16.h>
#include <math.h>
#include <float.h>
#include <stdint.h>

// Problem constants
constexpr int CB  = 2;
constexpr int CS  = 2048;
constexpr int CE  = 2048;
constexpr int CH  = 16;
constexpr int CKV = 8;
constexpr int CD  = 128;
constexpr int MROWS = CB * CS;          // 4096
constexpr int KVD   = CKV * CD;         // 1024
constexpr float RMS_EPS = 1.1920928955078125e-07f;
constexpr float ATTN_SCALE = 0.08838834764831845f;  // 1/sqrt(128)

// Scratch (device globals; no runtime allocation allowed)
__device__ float g_q[MROWS * CE];
__device__ float g_k[MROWS * KVD];
__device__ float g_v[MROWS * KVD];
__device__ float g_attn[MROWS * CE];

// ---------------------------------------------------------------------------
// Shared helpers: bf16 hi/lo split + bf16 mma
// ---------------------------------------------------------------------------
__device__ __forceinline__ void split2(float a, float b, uint32_t& hi, uint32_t& lo)
{
    __nv_bfloat16 ha = __float2bfloat16(a);
    __nv_bfloat16 hb = __float2bfloat16(b);
    float fa = __bfloat162float(ha), fb = __bfloat162float(hb);
    __nv_bfloat16 la = __float2bfloat16(a - fa);
    __nv_bfloat16 lb = __float2bfloat16(b - fb);
    hi = (uint32_t)__bfloat16_as_ushort(ha) | ((uint32_t)__bfloat16_as_ushort(hb) << 16);
    lo = (uint32_t)__bfloat16_as_ushort(la) | ((uint32_t)__bfloat16_as_ushort(lb) << 16);
}

__device__ __forceinline__ void mma_bf16(float (&c)[4],
    uint32_t a0, uint32_t a1, uint32_t a2, uint32_t a3,
    uint32_t b0, uint32_t b1)
{
    asm volatile(
        "mma.sync.aligned.m16n8k16.row.col.f32.bf16.bf16.f32 "
        "{%0,%1,%2,%3},{%4,%5,%6,%7},{%8,%9},{%0,%1,%2,%3};"
        : "+f"(c[0]), "+f"(c[1]), "+f"(c[2]), "+f"(c[3])
        : "r"(a0), "r"(a1), "r"(a2), "r"(a3), "r"(b0), "r"(b1));
}

// ---------------------------------------------------------------------------
// 3xBF16 tensor-core GEMM: C[M,N] = A[M,K] @ W[N,K]^T + bias[N]
// Block tile 128x128, BK=16, 256 threads (8 warps 2x4), warp tile 64x32.
// ---------------------------------------------------------------------------
constexpr int SW     = 12;              // smem row stride in 32-bit words (8 used + 4 pad)
constexpr int TILEW  = 128 * SW;        // 1536 words per tile
constexpr int STAGEW = 4 * TILEW;       // Ahi, Alo, Whi, Wlo
constexpr int GEMM_SMEM = 2 * STAGEW * 4;  // 49152 B

__global__ __launch_bounds__(256) void gemm_bf16x3_nt_bias(
    const float* __restrict__ A, const float* __restrict__ W,
    const float* __restrict__ bias, float* __restrict__ C,
    int Ndim, int Kdim)
{
    extern __shared__ uint32_t smw[];
    const int tid  = threadIdx.x;
    const int warp = tid >> 5, lane = tid & 31;
    const int wm = warp & 1, wn = warp >> 1;
    const int grp = lane >> 2, qd = lane & 3;
    const int row0 = blockIdx.y * 128;
    const int col0 = blockIdx.x * 128;

    const int ar = tid >> 2;             // 0..63 (rows ar, ar+64)
    const int kq = (tid & 3) << 2;       // 0,4,8,12
    const int kw = kq >> 1;              // word offset 0,2,4,6
    const float* Ap = A + (size_t)row0 * Kdim;
    const float* Wp = W + (size_t)col0 * Kdim;

    float acc[4][4][4];
    #pragma unroll
    for (int i = 0; i < 4; i++)
        #pragma unroll
        for (int j = 0; j < 4; j++)
            #pragma unroll
            for (int c = 0; c < 4; c++) acc[i][j][c] = 0.f;

    float4 ra0, ra1, rw0, rw1;
    const int NK = Kdim / 16;

    ra0 = *(const float4*)&Ap[(size_t)ar * Kdim + kq];
    ra1 = *(const float4*)&Ap[(size_t)(ar + 64) * Kdim + kq];
    rw0 = *(const float4*)&Wp[(size_t)ar * Kdim + kq];
    rw1 = *(const float4*)&Wp[(size_t)(ar + 64) * Kdim + kq];

    for (int ks = 0; ks < NK; ks++) {
        {
            uint32_t* st = smw + (ks & 1) * STAGEW;
            uint32_t* hA = st;
            uint32_t* lA = st + TILEW;
            uint32_t* hW = st + 2 * TILEW;
            uint32_t* lW = st + 3 * TILEW;
            const int o0 = ar * SW + kw;
            const int o1 = (ar + 64) * SW + kw;
            uint32_t h0, l0, h1, l1;
            split2(ra0.x, ra0.y, h0, l0); split2(ra0.z, ra0.w, h1, l1);
            hA[o0] = h0; hA[o0 + 1] = h1; lA[o0] = l0; lA[o0 + 1] = l1;
            split2(ra1.x, ra1.y, h0, l0); split2(ra1.z, ra1.w, h1, l1);
            hA[o1] = h0; hA[o1 + 1] = h1; lA[o1] = l0; lA[o1 + 1] = l1;
            split2(rw0.x, rw0.y, h0, l0); split2(rw0.z, rw0.w, h1, l1);
            hW[o0] = h0; hW[o0 + 1] = h1; lW[o0] = l0; lW[o0 + 1] = l1;
            split2(rw1.x, rw1.y, h0, l0); split2(rw1.z, rw1.w, h1, l1);
            hW[o1] = h0; hW[o1 + 1] = h1; lW[o1] = l0; lW[o1 + 1] = l1;
        }
        __syncthreads();

        if (ks + 1 < NK) {
            const int k0 = (ks + 1) * 16;
            ra0 = *(const float4*)&Ap[(size_t)ar * Kdim + k0 + kq];
            ra1 = *(const float4*)&Ap[(size_t)(ar + 64) * Kdim + k0 + kq];
            rw0 = *(const float4*)&Wp[(size_t)ar * Kdim + k0 + kq];
            rw1 = *(const float4*)&Wp[(size_t)(ar + 64) * Kdim + k0 + kq];
        }

        {
            const uint32_t* st = smw + (ks & 1) * STAGEW;
            const uint32_t* uAh = st;
            const uint32_t* uAl = st + TILEW;
            const uint32_t* uWh = st + 2 * TILEW;
            const uint32_t* uWl = st + 3 * TILEW;

            uint32_t ah[4][4], al[4][4], bh[4][2], bl[4][2];
            #pragma unroll
            for (int mt = 0; mt < 4; mt++) {
                const int m = wm * 64 + mt * 16;
                const int o0 = (m + grp) * SW + qd;
                const int o1 = o0 + 8 * SW;
                ah[mt][0] = uAh[o0]; ah[mt][1] = uAh[o1];
                ah[mt][2] = uAh[o0 + 4]; ah[mt][3] = uAh[o1 + 4];
                al[mt][0] = uAl[o0]; al[mt][1] = uAl[o1];
                al[mt][2] = uAl[o0 + 4]; al[mt][3] = uAl[o1 + 4];
            }
            #pragma unroll
            for (int nt = 0; nt < 4; nt++) {
                const int n = wn * 32 + nt * 8;
                const int bo = (n + grp) * SW + qd;
                bh[nt][0] = uWh[bo]; bh[nt][1] = uWh[bo + 4];
                bl[nt][0] = uWl[bo]; bl[nt][1] = uWl[bo + 4];
            }
            #pragma unroll
            for (int mt = 0; mt < 4; mt++)
                #pragma unroll
                for (int nt = 0; nt < 4; nt++)
                    mma_bf16(acc[mt][nt], ah[mt][0], ah[mt][1], ah[mt][2], ah[mt][3],
                             bh[nt][0], bh[nt][1]);
            #pragma unroll
            for (int mt = 0; mt < 4; mt++)
                #pragma unroll
                for (int nt = 0; nt < 4; nt++)
                    mma_bf16(acc[mt][nt], ah[mt][0], ah[mt][1], ah[mt][2], ah[mt][3],
                             bl[nt][0], bl[nt][1]);
            #pragma unroll
            for (int mt = 0; mt < 4; mt++)
                #pragma unroll
                for (int nt = 0; nt < 4; nt++)
                    mma_bf16(acc[mt][nt], al[mt][0], al[mt][1], al[mt][2], al[mt][3],
                             bh[nt][0], bh[nt][1]);
        }
        __syncthreads();
    }

    #pragma unroll
    for (int mt = 0; mt < 4; mt++) {
        const int row = row0 + wm * 64 + mt * 16 + grp;
        #pragma unroll
        for (int nt = 0; nt < 4; nt++) {
            const int col = col0 + wn * 32 + nt * 8 + 2 * qd;
            const float b0 = bias[col], b1 = bias[col + 1];
            float2 v0, v1;
            v0.x = acc[mt][nt][0] + b0; v0.y = acc[mt][nt][1] + b1;
            v1.x = acc[mt][nt][2] + b0; v1.y = acc[mt][nt][3] + b1;
            *(float2*)&C[(size_t)row * Ndim + col] = v0;
            *(float2*)&C[(size_t)(row + 8) * Ndim + col] = v1;
        }
    }
}

// ---------------------------------------------------------------------------
// RMSNorm over contiguous 128-element segments.
// ---------------------------------------------------------------------------
__global__ __launch_bounds__(128) void rmsnorm_kernel(
    float* __restrict__ buf, const float* __restrict__ w)
{
    __shared__ float red[4];
    float* p = buf + (size_t)blockIdx.x * CD;
    const int t = threadIdx.x;
    float v = p[t];
    float sq = v * v;
    #pragma unroll
    for (int o = 16; o > 0; o >>= 1) sq += __shfl_xor_sync(0xffffffffu, sq, o);
    if ((t & 31) == 0) red[t >> 5] = sq;
    __syncthreads();
    float ms = (red[0] + red[1] + red[2] + red[3]) * (1.0f / 128.0f);
    p[t] = v * rsqrtf(ms + RMS_EPS) * w[t];
}

// ---------------------------------------------------------------------------
// Flash attention, bf16x3 tensor cores. 128-query blocks, 64-key tiles.
// Grid: (S/128, H, B) with qt reversed (heavy blocks first). 256 threads.
// Warp w owns q-rows [16w, 16w+16). S-fragments repack in-register into
// PV A-fragments (no P smem round-trip).
// ---------------------------------------------------------------------------
constexpr int QSW = 68;   // Q/K row stride in words (64 used + 4 pad)
constexpr int VSW = 44;   // Vt row stride in words (32 used + 12 pad)
constexpr int OFF_QH = 0;
constexpr int OFF_QL = OFF_QH + 128 * QSW;   // 8704
constexpr int OFF_KH = OFF_QL + 128 * QSW;   // 17408
constexpr int OFF_KL = OFF_KH + 64 * QSW;    // 21760
constexpr int OFF_VH = OFF_KL + 64 * QSW;    // 26112
constexpr int OFF_VL = OFF_VH + 128 * VSW;   // 31744
constexpr int FLASH_WORDS = OFF_VL + 128 * VSW;  // 37376
constexpr int FLASH_SMEM = FLASH_WORDS * 4;      // 149504 B

__global__ __launch_bounds__(256) void flash_attn_mma(
    const float* __restrict__ Q, const float* __restrict__ K,
    const float* __restrict__ V, float* __restrict__ O)
{
    extern __shared__ uint32_t swd[];
    uint32_t* sQh = swd + OFF_QH;
    uint32_t* sQl = swd + OFF_QL;
    uint32_t* sKh = swd + OFF_KH;
    uint32_t* sKl = swd + OFF_KL;
    uint32_t* sVh = swd + OFF_VH;
    uint32_t* sVl = swd + OFF_VL;

    const int qt = gridDim.x - 1 - blockIdx.x;   // heavy blocks first
    const int h  = blockIdx.y;
    const int bb = blockIdx.z;
    const int kvh = h >> 1;                      // G = 2
    const int tid = threadIdx.x;
    const int warp = tid >> 5, lane = tid & 31;
    const int grp = lane >> 2, qd = lane & 3;
    const int q0 = qt * 128;
    const int rA = warp * 16 + grp;              // local q-row (and rA+8)

    // Load Q tile (128 rows x 64 words), split into bf16 hi/lo
    for (int i = tid; i < 128 * 64; i += 256) {
        const int r = i >> 6, wd = i & 63;
        float2 f = *(const float2*)&Q[((size_t)(bb * CS + q0 + r)) * CE + h * CD + 2 * wd];
        split2(f.x, f.y, sQh[r * QSW + wd], sQl[r * QSW + wd]);
    }

    float o[16][4];
    #pragma unroll
    for (int nt = 0; nt < 16; nt++)
        #pragma unroll
        for (int c = 0; c < 4; c++) o[nt][c] = 0.f;
    float m0 = -INFINITY, m1 = -INFINITY, l0 = 0.f, l1 = 0.f;

    const int nkt = 2 * qt + 2;   // 64-key tiles covering keys <= q0+127

    for (int kt = 0; kt < nkt; kt++) {
        const int k0 = kt * 64;
        __syncthreads();   // protect sK/sV from prior-iter readers (and sQ on first iter)

        // K tile (64 rows x 64 words)
        for (int i = tid; i < 64 * 64; i += 256) {
            const int r = i >> 6, wd = i & 63;
            float2 f = *(const float2*)&K[((size_t)(bb * CS + k0 + r)) * KVD + kvh * CD + 2 * wd];
            split2(f.x, f.y, sKh[r * QSW + wd], sKl[r * QSW + wd]);
        }
        // V tile transposed: word sV[d*VSW + j] packs keys (2j, 2j+1) at dim d
        for (int i = tid; i < 128 * 32; i += 256) {
            const int d = i & 127, j = i >> 7;
            const size_t base = ((size_t)(bb * CS + k0 + 2 * j)) * KVD + kvh * CD + d;
            split2(V[base], V[base + KVD], sVh[d * VSW + j], sVl[d * VSW + j]);
        }
        __syncthreads();

        // S = Q @ K^T (warp: 16 rows x 64 keys), 3-pass bf16
        float s[8][4];
        #pragma unroll
        for (int nt = 0; nt < 8; nt++)
            #pragma unroll
            for (int c = 0; c < 4; c++) s[nt][c] = 0.f;

        #pragma unroll
        for (int ks = 0; ks < 8; ks++) {
            const int ao  = rA * QSW + ks * 8 + qd;
            const int a1o = ao + 8 * QSW;
            const uint32_t ah0 = sQh[ao],  ah1 = sQh[a1o];
            const uint32_t ah2 = sQh[ao + 4], ah3 = sQh[a1o + 4];
            const uint32_t al0 = sQl[ao],  al1 = sQl[a1o];
            const uint32_t al2 = sQl[ao + 4], al3 = sQl[a1o + 4];
            #pragma unroll
            for (int nt = 0; nt < 8; nt++) {
                const int bo = (nt * 8 + grp) * QSW + ks * 8 + qd;
                const uint32_t bh0 = sKh[bo], bh1 = sKh[bo + 4];
                const uint32_t bl0 = sKl[bo], bl1 = sKl[bo + 4];
                mma_bf16(s[nt], ah0, ah1, ah2, ah3, bh0, bh1);
                mma_bf16(s[nt], ah0, ah1, ah2, ah3, bl0, bl1);
                mma_bf16(s[nt], al0, al1, al2, al3, bh0, bh1);
            }
        }

        // scale + causal mask
        const int gr0 = q0 + rA, gr1 = gr0 + 8;
        #pragma unroll
        for (int nt = 0; nt < 8; nt++) {
            const int gc = k0 + nt * 8 + 2 * qd;
            s[nt][0] = (gc     > gr0) ? -1e30f : s[nt][0] * ATTN_SCALE;
            s[nt][1] = (gc + 1 > gr0) ? -1e30f : s[nt][1] * ATTN_SCALE;
            s[nt][2] = (gc     > gr1) ? -1e30f : s[nt][2] * ATTN_SCALE;
            s[nt][3] = (gc + 1 > gr1) ? -1e30f : s[nt][3] * ATTN_SCALE;
        }

        // online softmax (rows rA, rA+8; row spread across quad lanes)
        float mx0 = -INFINITY, mx1 = -INFINITY;
        #pragma unroll
        for (int nt = 0; nt < 8; nt++) {
            mx0 = fmaxf(mx0, fmaxf(s[nt][0], s[nt][1]));
            mx1 = fmaxf(mx1, fmaxf(s[nt][2], s[nt][3]));
        }
        mx0 = fmaxf(mx0, __shfl_xor_sync(0xffffffffu, mx0, 1));
        mx0 = fmaxf(mx0, __shfl_xor_sync(0xffffffffu, mx0, 2));
        mx1 = fmaxf(mx1, __shfl_xor_sync(0xffffffffu, mx1, 1));
        mx1 = fmaxf(mx1, __shfl_xor_sync(0xffffffffu, mx1, 2));
        const float mn0 = fmaxf(m0, mx0), mn1 = fmaxf(m1, mx1);
        const float c0 = __expf(m0 - mn0), c1 = __expf(m1 - mn1);
        float rs0 = 0.f, rs1 = 0.f;
        #pragma unroll
        for (int nt = 0; nt < 8; nt++) {
            s[nt][0] = __expf(s[nt][0] - mn0); rs0 += s[nt][0];
            s[nt][1] = __expf(s[nt][1] - mn0); rs0 += s[nt][1];
            s[nt][2] = __expf(s[nt][2] - mn1); rs1 += s[nt][2];
            s[nt][3] = __expf(s[nt][3] - mn1); rs1 += s[nt][3];
        }
        rs0 += __shfl_xor_sync(0xffffffffu, rs0, 1);
        rs0 += __shfl_xor_sync(0xffffffffu, rs0, 2);
        rs1 += __shfl_xor_sync(0xffffffffu, rs1, 1);
        rs1 += __shfl_xor_sync(0xffffffffu, rs1, 2);
        l0 = l0 * c0 + rs0; l1 = l1 * c1 + rs1;
        m0 = mn0; m1 = mn1;
        #pragma unroll
        for (int nt = 0; nt < 16; nt++) {
            o[nt][0] *= c0; o[nt][1] *= c0;
            o[nt][2] *= c1; o[nt][3] *= c1;
        }

        // O += P @ V : P repacked in-register (S frag -> A frag), V from smem
        #pragma unroll
        for (int ks = 0; ks < 4; ks++) {
            uint32_t pa0h, pa0l, pa1h, pa1l, pa2h, pa2l, pa3h, pa3l;
            split2(s[2 * ks][0],     s[2 * ks][1],     pa0h, pa0l);
            split2(s[2 * ks][2],     s[2 * ks][3],     pa1h, pa1l);
            split2(s[2 * ks + 1][0], s[2 * ks + 1][1], pa2h, pa2l);
            split2(s[2 * ks + 1][2], s[2 * ks + 1][3], pa3h, pa3l);
            #pragma unroll
            for (int nt = 0; nt < 16; nt++) {
                const int bo = (nt * 8 + grp) * VSW + ks * 8 + qd;
                const uint32_t bh0 = sVh[bo], bh1 = sVh[bo + 4];
                const uint32_t bl0 = sVl[bo], bl1 = sVl[bo + 4];
                mma_bf16(o[nt], pa0h, pa1h, pa2h, pa3h, bh0, bh1);
                mma_bf16(o[nt], pa0h, pa1h, pa2h, pa3h, bl0, bl1);
                mma_bf16(o[nt], pa0l, pa1l, pa2l, pa3l, bh0, bh1);
            }
        }
    }

    // epilogue
    const float i0 = 1.0f / l0, i1 = 1.0f / l1;
    const size_t ro0 = ((size_t)(bb * CS + q0 + rA)) * CE + h * CD;
    const size_t ro1 = ro0 + (size_t)8 * CE;
    #pragma unroll
    for (int nt = 0; nt < 16; nt++) {
        const int c = nt * 8 + 2 * qd;
        float2 w0, w1;
        w0.x = o[nt][0] * i0; w0.y = o[nt][1] * i0;
        w1.x = o[nt][2] * i1; w1.y = o[nt][3] * i1;
        *(float2*)&O[ro0 + c] = w0;
        *(float2*)&O[ro1 + c] = w1;
    }
}

// ---------------------------------------------------------------------------
// Launch
// ---------------------------------------------------------------------------
extern "C" void kernel_launch(void* const* d_in, const int* in_sizes, int n_in,
                              void* d_out, int out_size)
{
    (void)in_sizes; (void)n_in; (void)out_size;
    const float* x  = (const float*)d_in[0];
    const float* Wq = (const float*)d_in[1];
    const float* bq = (const float*)d_in[2];
    const float* Wk = (const float*)d_in[3];
    const float* bk = (const float*)d_in[4];
    const float* Wv = (const float*)d_in[5];
    const float* bv = (const float*)d_in[6];
    const float* Wo = (const float*)d_in[7];
    const float* bo = (const float*)d_in[8];
    const float* qn = (const float*)d_in[9];
    const float* kn = (const float*)d_in[10];
    float* out = (float*)d_out;

    float *q, *k, *v, *attn;
    cudaGetSymbolAddress((void**)&q,    g_q);
    cudaGetSymbolAddress((void**)&k,    g_k);
    cudaGetSymbolAddress((void**)&v,    g_v);
    cudaGetSymbolAddress((void**)&attn, g_attn);

    (void)cudaFuncSetAttribute(gemm_bf16x3_nt_bias,
                               cudaFuncAttributeMaxDynamicSharedMemorySize,
                               GEMM_SMEM);
    (void)cudaFuncSetAttribute(flash_attn_mma,
                               cudaFuncAttributeMaxDynamicSharedMemorySize,
                               FLASH_SMEM);

    dim3 gE(CE / 128, MROWS / 128);    // (16, 32)
    dim3 gKV(KVD / 128, MROWS / 128);  // (8, 32)

    gemm_bf16x3_nt_bias<<<gE, 256, GEMM_SMEM>>>(x, Wq, bq, q, CE, CE);
    gemm_bf16x3_nt_bias<<<gKV, 256, GEMM_SMEM>>>(x, Wk, bk, k, KVD, CE);
    gemm_bf16x3_nt_bias<<<gKV, 256, GEMM_SMEM>>>(x, Wv, bv, v, KVD, CE);

    rmsnorm_kernel<<<MROWS * CH, 128>>>(q, qn);
    rmsnorm_kernel<<<MROWS * CKV, 128>>>(k, kn);

    dim3 ga(CS / 128, CH, CB);         // (16, 16, 2)
    flash_attn_mma<<<ga, 256, FLASH_SMEM>>>(q, k, v, attn);

    gemm_bf16x3_nt_bias<<<gE, 256, GEMM_SMEM>>>(attn, Wo, bo, out, CE, CE);
}